// round 11
// baseline (speedup 1.0000x reference)
#include <cuda_runtime.h>
#include <cuda_fp16.h>
#include <cstdint>
#include <cstddef>

#define KP      32832            // 32768 + 64 bias/pad columns
#define KC      32               // K per pipeline chunk
#define NCHUNK  (KP / KC)        // 1026
#define ROWP    40               // smem row pitch in halves (80B, conflict-free)
#define STG_H   (128 * ROWP)     // halves per operand per stage (5120)
#define STAGE_B (2 * STG_H * 2)  // bytes per stage: A + B = 20480
#define SMEM_SZ (4 * STAGE_B)    // 81920 (x2 CTAs = 160 KB/SM, fits 228 KB)

__device__ __align__(1024) __half g_z[(size_t)4096 * KP];   // 257 MiB
__device__ __align__(1024) __half g_w[(size_t)1024 * KP];   //  64 MiB

#define DEV_INLINE __device__ __forceinline__

DEV_INLINE uint32_t smem_u32(const void* p) { return (uint32_t)__cvta_generic_to_shared(p); }

DEV_INLINE void ldsm4(uint32_t* r, uint32_t addr) {
    asm volatile("ldmatrix.sync.aligned.m8n8.x4.shared.b16 {%0,%1,%2,%3}, [%4];"
                 : "=r"(r[0]), "=r"(r[1]), "=r"(r[2]), "=r"(r[3]) : "r"(addr));
}

DEV_INLINE void mma16816(float* c, const uint32_t* a, uint32_t b0, uint32_t b1) {
    asm volatile("mma.sync.aligned.m16n8k16.row.col.f32.f16.f16.f32 "
                 "{%0,%1,%2,%3}, {%4,%5,%6,%7}, {%8,%9}, {%0,%1,%2,%3};"
                 : "+f"(c[0]), "+f"(c[1]), "+f"(c[2]), "+f"(c[3])
                 : "r"(a[0]), "r"(a[1]), "r"(a[2]), "r"(a[3]), "r"(b0), "r"(b1));
}

DEV_INLINE void cp16(uint32_t dst, const void* src) {
    asm volatile("cp.async.cg.shared.global [%0], [%1], 16;" :: "r"(dst), "l"(src));
}

// ---------------------------------------------------------------------------
// K1 (fused): gates = softmax(x@gw+gb); z[b,i*32+l] = x[b,i]*g[b,l]; tail.
// grid 4096 x 256
// ---------------------------------------------------------------------------
__global__ void k_prep(const float* __restrict__ x, const float* __restrict__ gw,
                       const float* __restrict__ gb) {
    __shared__ float xs[1024];
    __shared__ float part[256];
    __shared__ float gs[32];
    int b = blockIdx.x, t = threadIdx.x;
    for (int i = t; i < 1024; i += 256) xs[i] = x[(size_t)b * 1024 + i];
    __syncthreads();
    int l = t & 31, p = t >> 5;
    float s = 0.f;
    #pragma unroll 4
    for (int i = p * 128; i < p * 128 + 128; i++) s += xs[i] * gw[i * 32 + l];
    part[t] = s;
    __syncthreads();
    if (t < 32) {
        float v = gb[t];
        #pragma unroll
        for (int q = 0; q < 8; q++) v += part[q * 32 + t];
        float mx = v;
        for (int o = 16; o; o >>= 1) mx = fmaxf(mx, __shfl_xor_sync(~0u, mx, o));
        float e = __expf(v - mx), se = e;
        for (int o = 16; o; o >>= 1) se += __shfl_xor_sync(~0u, se, o);
        gs[t] = e / se;
    }
    __syncthreads();
    __half* zr = g_z + (size_t)b * KP;
    if (t < 64) zr[32768 + t] = __float2half(t < 32 ? gs[t] : 0.f);
    for (int i = t; i < 1024; i += 256) {
        float xv = xs[i];
        __align__(16) __half2 buf[16];
        #pragma unroll
        for (int j = 0; j < 32; j += 2)
            buf[j >> 1] = __floats2half2_rn(xv * gs[j], xv * gs[j + 1]);
        uint4* dst = (uint4*)(zr + (size_t)i * 32);
        const uint4* sb4 = (const uint4*)buf;
        dst[0] = sb4[0]; dst[1] = sb4[1]; dst[2] = sb4[2]; dst[3] = sb4[3];
    }
}

// ---------------------------------------------------------------------------
// K2 (fused): W fp16 convert + bias/pad columns.  grid 32832 x 256
// (pw already [o][i][l] = K-major over (i,l))
// ---------------------------------------------------------------------------
__global__ void k_w(const float* __restrict__ pw, const float* __restrict__ pb) {
    int idx = blockIdx.x * 256 + threadIdx.x;              // < 8404992
    int o = idx / 8208, v = idx - o * 8208;
    int k = v * 4;
    __half* dst = g_w + (size_t)o * KP + k;
    if (k < 32768) {
        float4 f = *(const float4*)(pw + (size_t)o * 32768 + k);
        __half2 h0 = __floats2half2_rn(f.x, f.y), h1 = __floats2half2_rn(f.z, f.w);
        uint2 u;
        u.x = *(const uint32_t*)&h0; u.y = *(const uint32_t*)&h1;
        *(uint2*)dst = u;
    } else {
        int l = k - 32768;
        #pragma unroll
        for (int j = 0; j < 4; j++)
            dst[j] = __float2half((l + j) < 32 ? pb[o * 32 + l + j] : 0.f);
    }
}

// ---------------------------------------------------------------------------
// K3: GEMM out[4096,1024] = z @ W^T.  Tile 128x128, Kc=32, 4-stage cp.async,
//     ldmatrix + mma.sync.m16n8k16, 2 CTAs/SM, single barrier per chunk.
// ---------------------------------------------------------------------------
DEV_INLINE void load_chunk(const __half* A, const __half* Bm, uint32_t sa, int c, int t) {
    const size_t koff = (size_t)c * KC;
    #pragma unroll
    for (int u = 0; u < 2; u++) {                 // A: 128 rows x 2 x 16B
        int idx = t + u * 256, r = idx >> 2, j = idx & 3;
        cp16(sa + (uint32_t)(r * ROWP + j * 8) * 2, A + (size_t)r * KP + koff + j * 8);
    }
    uint32_t sb = sa + STG_H * 2;
    #pragma unroll
    for (int u = 0; u < 2; u++) {                 // B: 128 rows x 2 x 16B
        int idx = t + u * 256, r = idx >> 2, j = idx & 3;
        cp16(sb + (uint32_t)(r * ROWP + j * 8) * 2, Bm + (size_t)r * KP + koff + j * 8);
    }
}

__global__ void __launch_bounds__(256, 2) k_gemm(float* __restrict__ out) {
    extern __shared__ char smem[];
    const uint32_t sbase = smem_u32(smem);
    const int t = threadIdx.x, w = t >> 5, lane = t & 31;
    const int wm = w & 3, wn = w >> 2;            // warp tile: rows wm*32, cols wn*64

    const int m0 = blockIdx.y * 128, n0 = blockIdx.x * 128;
    const __half* A  = g_z + (size_t)m0 * KP;
    const __half* Bm = g_w + (size_t)n0 * KP;

    float acc[2][8][4];
    #pragma unroll
    for (int i = 0; i < 2; i++)
        #pragma unroll
        for (int j = 0; j < 8; j++)
            #pragma unroll
            for (int q = 0; q < 4; q++) acc[i][j][q] = 0.f;

    const int lrow = lane & 15, lcol = (lane >> 4) * 8;

    #pragma unroll
    for (int c = 0; c < 3; c++) {                 // prologue
        load_chunk(A, Bm, sbase + (uint32_t)c * STAGE_B, c, t);
        asm volatile("cp.async.commit_group;");
    }

    for (int c = 0; c < NCHUNK; c++) {
        asm volatile("cp.async.wait_group 2;");   // chunk c resident
        __syncthreads();                          // all warps past compute(c-1)
        int cn = c + 3;
        if (cn < NCHUNK)                          // overwrite stage of chunk c-1
            load_chunk(A, Bm, sbase + (uint32_t)(cn & 3) * STAGE_B, cn, t);
        asm volatile("cp.async.commit_group;");   // unconditional: keep counts uniform

        uint32_t sA = sbase + (uint32_t)(c & 3) * STAGE_B;
        uint32_t sB = sA + STG_H * 2;
        #pragma unroll
        for (int ks = 0; ks < 2; ks++) {
            const int k0 = ks * 16;
            uint32_t a[2][4], b[4][4];
            #pragma unroll
            for (int mt = 0; mt < 2; mt++)
                ldsm4(a[mt], sA + (uint32_t)((wm * 32 + mt * 16 + lrow) * ROWP + k0 + lcol) * 2);
            #pragma unroll
            for (int q = 0; q < 4; q++)
                ldsm4(b[q], sB + (uint32_t)((wn * 64 + q * 16 + lrow) * ROWP + k0 + lcol) * 2);
            #pragma unroll
            for (int mt = 0; mt < 2; mt++)
                #pragma unroll
                for (int n8 = 0; n8 < 8; n8++) {
                    int q = n8 >> 1, hi = n8 & 1;
                    mma16816(acc[mt][n8], a[mt], b[q][hi], b[q][hi + 2]);
                }
        }
    }

    // Epilogue
    const int rbase = m0 + wm * 32 + (lane >> 2);
    const int cbase = n0 + wn * 64 + (lane & 3) * 2;
    #pragma unroll
    for (int mt = 0; mt < 2; mt++)
        #pragma unroll
        for (int n8 = 0; n8 < 8; n8++) {
            float* p0 = out + (size_t)(rbase + mt * 16) * 1024 + cbase + n8 * 8;
            float* p1 = p0 + 8 * 1024;
            *(float2*)p0 = make_float2(acc[mt][n8][0], acc[mt][n8][1]);
            *(float2*)p1 = make_float2(acc[mt][n8][2], acc[mt][n8][3]);
        }
}

// ---------------------------------------------------------------------------
extern "C" void kernel_launch(void* const* d_in, const int* in_sizes, int n_in,
                              void* d_out, int out_size) {
    const float* x  = (const float*)d_in[0];
    const float* gw = (const float*)d_in[1];
    const float* gb = (const float*)d_in[2];
    const float* pw = (const float*)d_in[3];
    const float* pb = (const float*)d_in[4];
    float* out = (float*)d_out;

    cudaFuncSetAttribute(k_gemm, cudaFuncAttributeMaxDynamicSharedMemorySize, SMEM_SZ);

    k_prep<<<4096, 256>>>(x, gw, gb);
    k_w   <<<32832, 256>>>(pw, pb);
    k_gemm<<<dim3(8, 32), 256, SMEM_SZ>>>(out);
}

// round 16
// speedup vs baseline: 1.0741x; 1.0741x over previous
#include <cuda_runtime.h>
#include <cuda_fp16.h>
#include <cstdint>
#include <cstddef>

#define KP      32832            // W row stride: 32768 + 64 (bias+pad)
#define KC      64               // K per chunk (= 2 x-columns)
#define CHUNKS  513              // K chunks per tile (512 x-pairs + 1 bias chunk)
#define NTILES  256              // 32 (M) x 8 (N) tiles of 128x128
#define UNITS   (NTILES * CHUNKS)  // 131328
#define NW      296              // workers = 2 per SM x 148
#define ROWB    144              // smem row stride bytes (72 halves, conflict-free)
#define BSTG    (128 * ROWB)     // 18432 B per B stage
#define XSTG    1024             // 2 x-columns (fp32) per stage
#define STGB    (BSTG + XSTG)    // 19456
#define AOFF    (4 * STGB)       // 77824: single A buffer
#define GOFF    (AOFF + BSTG)    // 96256: gate tile fp32, 128 rows x 34 floats
#define GSTR    136
#define SMEM_SZ (GOFF + 128 * GSTR)   // 113664 (x2 CTAs = 227 KB/SM)

__device__ __align__(1024) __half g_w[(size_t)1024 * KP];   // 64 MiB fp16 W
__device__ __align__(16) float g_gatef[4096 * 32];

#define DEV_INLINE __device__ __forceinline__

DEV_INLINE uint32_t smem_u32(const void* p) { return (uint32_t)__cvta_generic_to_shared(p); }

DEV_INLINE void ldsm4(uint32_t* r, uint32_t addr) {
    asm volatile("ldmatrix.sync.aligned.m8n8.x4.shared.b16 {%0,%1,%2,%3}, [%4];"
                 : "=r"(r[0]), "=r"(r[1]), "=r"(r[2]), "=r"(r[3]) : "r"(addr));
}

DEV_INLINE void mma16816(float* c, const uint32_t* a, uint32_t b0, uint32_t b1) {
    asm volatile("mma.sync.aligned.m16n8k16.row.col.f32.f16.f16.f32 "
                 "{%0,%1,%2,%3}, {%4,%5,%6,%7}, {%8,%9}, {%0,%1,%2,%3};"
                 : "+f"(c[0]), "+f"(c[1]), "+f"(c[2]), "+f"(c[3])
                 : "r"(a[0]), "r"(a[1]), "r"(a[2]), "r"(a[3]), "r"(b0), "r"(b1));
}

DEV_INLINE void cp16(uint32_t dst, const void* src) {
    asm volatile("cp.async.cg.shared.global [%0], [%1], 16;" :: "r"(dst), "l"(src));
}

// ---------------------------------------------------------------------------
// K0: zero the output (atomicAdd accumulation target).  grid 4096 x 256
// ---------------------------------------------------------------------------
__global__ void k_zero(float4* __restrict__ out) {
    out[blockIdx.x * 256 + threadIdx.x] = make_float4(0.f, 0.f, 0.f, 0.f);
}

// ---------------------------------------------------------------------------
// K1: gates = softmax(x@gw+gb), warp per row.  grid 512 x 256
// ---------------------------------------------------------------------------
__global__ void k_gates(const float* __restrict__ x, const float* __restrict__ gw,
                        const float* __restrict__ gb) {
    int row = blockIdx.x * 8 + (threadIdx.x >> 5);
    int lane = threadIdx.x & 31;
    const float* xr = x + (size_t)row * 1024;
    float s = 0.f;
    for (int i0 = 0; i0 < 1024; i0 += 32) {
        float xv = xr[i0 + lane];
        #pragma unroll
        for (int j = 0; j < 32; j++) {
            float xb = __shfl_sync(~0u, xv, j);
            s = fmaf(xb, gw[(i0 + j) * 32 + lane], s);
        }
    }
    float v = s + gb[lane];
    float mx = v;
    for (int o = 16; o; o >>= 1) mx = fmaxf(mx, __shfl_xor_sync(~0u, mx, o));
    float e = __expf(v - mx), se = e;
    for (int o = 16; o; o >>= 1) se += __shfl_xor_sync(~0u, se, o);
    g_gatef[row * 32 + lane] = e / se;
}

// ---------------------------------------------------------------------------
// K2: W fp16 convert + bias/pad columns.  grid 32832 x 256
// ---------------------------------------------------------------------------
__global__ void k_w(const float* __restrict__ pw, const float* __restrict__ pb) {
    int idx = blockIdx.x * 256 + threadIdx.x;
    int o = idx / 8208, v = idx - o * 8208;
    int k = v * 4;
    __half* dst = g_w + (size_t)o * KP + k;
    if (k < 32768) {
        float4 f = *(const float4*)(pw + (size_t)o * 32768 + k);
        __half2 h0 = __floats2half2_rn(f.x, f.y), h1 = __floats2half2_rn(f.z, f.w);
        uint2 u;
        u.x = *(const uint32_t*)&h0; u.y = *(const uint32_t*)&h1;
        *(uint2*)dst = u;
    } else {
        int l = k - 32768;
        #pragma unroll
        for (int j = 0; j < 4; j++)
            dst[j] = __float2half((l + j) < 32 ? pb[o * 32 + l + j] : 0.f);
    }
}

// ---------------------------------------------------------------------------
// K3: balanced-K GEMM with on-the-fly A = x-col (x) gates outer product.
// ---------------------------------------------------------------------------
DEV_INLINE void load_stage(uint32_t sbase, int s, int c, int m0, int n0, int t,
                           const float* __restrict__ x) {
    uint32_t sb = sbase + (uint32_t)s * STGB;
    size_t koff = (size_t)c * KC;
    #pragma unroll
    for (int u = 0; u < 4; u++) {                 // B: 128 rows x 128B (fp16)
        int idx = t + u * 256, r = idx >> 3, j = idx & 7;
        cp16(sb + (uint32_t)(r * ROWB + j * 16),
             g_w + (size_t)(n0 + r) * KP + koff + j * 8);
    }
    if (c < 512) {                                // 2 x-columns, 4B each thread
        int r = t & 127, h = t >> 7;
        asm volatile("cp.async.ca.shared.global [%0], [%1], 4;"
            :: "r"(sb + BSTG + (uint32_t)((h * 128 + r) * 4)),
               "l"(x + (size_t)(m0 + r) * 1024 + c * 2 + h));
    }
}

__global__ void __launch_bounds__(256, 2) k_gemm(float* __restrict__ out,
                                                 const float* __restrict__ x) {
    extern __shared__ char smem[];
    const uint32_t sbase = smem_u32(smem);
    const int t = threadIdx.x, w = t >> 5, lane = t & 31;
    const int wm = w & 3, wn = w >> 2;            // warp tile 32(m) x 64(n)
    const int lrow = lane & 15, lcol = (lane >> 4) * 8;
    const int br = t & 127, bh = t >> 7;          // A-build role: row, half

    uint64_t u  = ((uint64_t)blockIdx.x * UNITS) / NW;
    uint64_t eu = ((uint64_t)(blockIdx.x + 1) * UNITS) / NW;

    while (u < eu) {
        int tile = (int)(u / CHUNKS), c0 = (int)(u % CHUNKS);
        uint64_t span = eu - u;
        int c1 = (span < (uint64_t)(CHUNKS - c0)) ? c0 + (int)span : CHUNKS;
        int m0 = (tile >> 3) * 128, n0 = (tile & 7) * 128;

        asm volatile("cp.async.wait_group 0;" ::: "memory");
        __syncthreads();                          // prev segment fully done
        {   // stage gate tile (fp32), float2 ops: GSTR=136 is 8B-aligned per row
            const float2* gsrc = (const float2*)(g_gatef + (size_t)(m0 + br) * 32 + bh * 16);
            float2* gdst = (float2*)(smem + GOFF + br * GSTR + bh * 64);
            #pragma unroll
            for (int j = 0; j < 8; j++) gdst[j] = gsrc[j];
        }

        float acc[2][8][4] = {};

        #pragma unroll
        for (int p = 0; p < 3; p++) {             // prologue (pads empty groups)
            if (p < c1 - c0) load_stage(sbase, p, c0 + p, m0, n0, t, x);
            asm volatile("cp.async.commit_group;" ::: "memory");
        }

        for (int c = c0; c < c1; ++c) {
            int s = (c - c0) & 3;
            asm volatile("cp.async.wait_group 2;" ::: "memory");
            __syncthreads();                      // chunk c resident; compute(c-1) done
            if (c + 3 < c1) load_stage(sbase, (s + 3) & 3, c + 3, m0, n0, t, x);
            asm volatile("cp.async.commit_group;" ::: "memory");

            // build fp16 A tile: A[r][h*32+l] = x[r][2c+h] * g[r][l]
            {
                const float* Gf = (const float*)(smem + GOFF + br * GSTR);
                __align__(16) __half2 vals[16];
                if (c < 512) {
                    float xv = *(const float*)(smem + (size_t)s * STGB + BSTG + (bh * 128 + br) * 4);
                    #pragma unroll
                    for (int j = 0; j < 16; j++)
                        vals[j] = __floats2half2_rn(xv * Gf[2 * j], xv * Gf[2 * j + 1]);
                } else if (bh == 0) {             // bias chunk: A = g row
                    #pragma unroll
                    for (int j = 0; j < 16; j++)
                        vals[j] = __floats2half2_rn(Gf[2 * j], Gf[2 * j + 1]);
                } else {                          // zero pad columns
                    #pragma unroll
                    for (int j = 0; j < 16; j++)
                        vals[j] = __floats2half2_rn(0.f, 0.f);
                }
                float4* adst = (float4*)(smem + AOFF + br * ROWB + bh * 64);
                const float4* vs = (const float4*)vals;
                adst[0] = vs[0]; adst[1] = vs[1]; adst[2] = vs[2]; adst[3] = vs[3];
            }
            __syncthreads();                      // A ready for ldsm

            uint32_t sB = sbase + (uint32_t)s * STGB;
            uint32_t sA = sbase + AOFF;
            #pragma unroll
            for (int ks = 0; ks < 4; ks++) {
                const int k0 = ks * 16;
                uint32_t a[2][4], b[4][4];
                #pragma unroll
                for (int mt = 0; mt < 2; mt++)
                    ldsm4(a[mt], sA + (uint32_t)((wm * 32 + mt * 16 + lrow) * ROWB + (k0 + lcol) * 2));
                #pragma unroll
                for (int q = 0; q < 4; q++)
                    ldsm4(b[q], sB + (uint32_t)((wn * 64 + q * 16 + lrow) * ROWB + (k0 + lcol) * 2));
                #pragma unroll
                for (int mt = 0; mt < 2; mt++)
                    #pragma unroll
                    for (int n8 = 0; n8 < 8; n8++) {
                        int q = n8 >> 1, hi = n8 & 1;
                        mma16816(acc[mt][n8], a[mt], b[q][hi], b[q][hi + 2]);
                    }
            }
        }

        // epilogue: accumulate partial tile into out
        const int rbase = m0 + wm * 32 + (lane >> 2);
        const int cbase = n0 + wn * 64 + (lane & 3) * 2;
        #pragma unroll
        for (int mt = 0; mt < 2; mt++)
            #pragma unroll
            for (int n8 = 0; n8 < 8; n8++) {
                float* p0 = out + (size_t)(rbase + mt * 16) * 1024 + cbase + n8 * 8;
                atomicAdd(p0,        acc[mt][n8][0]);
                atomicAdd(p0 + 1,    acc[mt][n8][1]);
                atomicAdd(p0 + 8192, acc[mt][n8][2]);   // +8 rows
                atomicAdd(p0 + 8193, acc[mt][n8][3]);
            }

        u += (uint64_t)(c1 - c0);
    }
}

// ---------------------------------------------------------------------------
extern "C" void kernel_launch(void* const* d_in, const int* in_sizes, int n_in,
                              void* d_out, int out_size) {
    const float* x  = (const float*)d_in[0];
    const float* gw = (const float*)d_in[1];
    const float* gb = (const float*)d_in[2];
    const float* pw = (const float*)d_in[3];
    const float* pb = (const float*)d_in[4];
    float* out = (float*)d_out;

    cudaFuncSetAttribute(k_gemm, cudaFuncAttributeMaxDynamicSharedMemorySize, SMEM_SZ);

    k_zero <<<4096, 256>>>((float4*)out);
    k_gates<<<512, 256>>>(x, gw, gb);
    k_w    <<<32832, 256>>>(pw, pb);
    k_gemm <<<NW, 256, SMEM_SZ>>>(out, x);
}